// round 15
// baseline (speedup 1.0000x reference)
#include <cuda_runtime.h>
#include <cstdint>

#define N_ROWS  32768
#define D_DIM   256
#define K_CODES 2048
#define K3      768                 // 3 tf32 segments of 256
#define BM      256                 // rows per CTA
#define BN      128                 // codes per pass tile
#define BK      32                  // k per chunk
#define NBLK    (N_ROWS / BM)       // 128
#define PASSES  (K_CODES / BN)      // 16
#define NCHUNK  (K3 / BK)           // 24
#define EPS_FLAG 1.2e-4f            // > 2 score-grid steps + margin
#define GBLK    256                 // gather kernel blocks (128 rows each)

typedef unsigned int u32;

// static device scratch — PRE-PACKED fragment layouts:
// XA[rowTile(2048)][chunk(24)][s(4)][lane(32)][4] :
//   lane l=g*4+t -> {Ahi/lo[g][t], [g+8][t], [g][t+4], [g+8][t+4]} (16-row tile)
// CB[codeTile(128)][chunk(24)][s(4)][lane(32)][4] :
//   lane l=g*4+t -> {B[g][t], B[g][t+4], B[g+8][t], B[g+8][t+4]}  (16-code tile)
__device__ float XA[(size_t)N_ROWS * K3];
__device__ float CB[(size_t)K_CODES * K3];
__device__ float g_xnorm[N_ROWS];
__device__ float g_cnorm[K_CODES];
__device__ float g_partial[GBLK];
__device__ int   g_widx[N_ROWS];
__device__ int   g_flaglist[N_ROWS];
__device__ int   g_flagcnt;

// ---------------- helpers (baseline PTX only) ------------------------------
__device__ __forceinline__ u32 smem_u32(const void* p) {
    u32 a;
    asm("{ .reg .u64 t; cvta.to.shared.u64 t, %1; cvt.u32.u64 %0, t; }" : "=r"(a) : "l"(p));
    return a;
}
__device__ __forceinline__ float tf32_rna(float a) {
    u32 r;
    asm("cvt.rna.tf32.f32 %0, %1;" : "=r"(r) : "f"(a));
    return __uint_as_float(r);
}
__device__ __forceinline__ void cp_async16(u32 dst, const void* src) {
    asm volatile("cp.async.cg.shared.global [%0], [%1], 16;" :: "r"(dst), "l"(src));
}
#define CP_COMMIT()  asm volatile("cp.async.commit_group;")
#define CP_WAIT(n)   asm volatile("cp.async.wait_group %0;" :: "n"(n))

__device__ __forceinline__ void mma_tf32(float* c, u32 a0, u32 a1, u32 a2, u32 a3,
                                         u32 b0, u32 b1) {
    asm volatile(
        "mma.sync.aligned.m16n8k8.row.col.f32.tf32.tf32.f32 "
        "{%0,%1,%2,%3}, {%4,%5,%6,%7}, {%8,%9}, {%0,%1,%2,%3};"
        : "+f"(c[0]), "+f"(c[1]), "+f"(c[2]), "+f"(c[3])
        : "r"(a0), "r"(a1), "r"(a2), "r"(a3), "r"(b0), "r"(b1));
}

__global__ void zero_kernel() { g_flagcnt = 0; }

// ---------------------------------------------------------------------------
// FROZEN: bit-exact XLA row-sumsq (256-wide f32).
// ---------------------------------------------------------------------------
__device__ __forceinline__ float xla_row_sumsq(const float* __restrict__ row, int lane) {
    float s[4];
#pragma unroll
    for (int g = 0; g < 4; g++) {
        float x0 = row[64 * g + 2 * lane];
        float x1 = row[64 * g + 2 * lane + 1];
        s[g] = __fadd_rn(__fmul_rn(x0, x0), __fmul_rn(x1, x1));
    }
#pragma unroll
    for (int off = 16; off > 0; off >>= 1) {
#pragma unroll
        for (int g = 0; g < 4; g++)
            s[g] = __fadd_rn(s[g], __shfl_down_sync(0xffffffffu, s[g], off));
    }
    return __fadd_rn(__fadd_rn(s[0], s[2]), __fadd_rn(s[1], s[3]));
}

__global__ void norms_kernel(const float* __restrict__ x, const float* __restrict__ cb) {
    int warp = (blockIdx.x * blockDim.x + threadIdx.x) >> 5;
    int lane = threadIdx.x & 31;
    if (warp < N_ROWS) {
        float a = xla_row_sumsq(x + (size_t)warp * D_DIM, lane);
        if (lane == 0) g_xnorm[warp] = a;
    } else if (warp < N_ROWS + K_CODES) {
        int j = warp - N_ROWS;
        float b = xla_row_sumsq(cb + (size_t)j * D_DIM, lane);
        if (lane == 0) g_cnorm[j] = b;
    }
}

// ---------------------------------------------------------------------------
// Packed tf32x3 split builders.
//   A k-order: [hi | hi | lo]   (seg = k/256)
//   B k-order: [hi | lo | hi]
// ---------------------------------------------------------------------------
__device__ __forceinline__ float xa_val(const float* __restrict__ x, int row, int kk) {
    int seg = kk >> 8, kin = kk & 255;
    float v = x[(size_t)row * D_DIM + kin];
    float h = tf32_rna(v);
    return (seg == 2) ? tf32_rna(__fsub_rn(v, h)) : h;
}
__device__ __forceinline__ float cb_val(const float* __restrict__ cb, int row, int kk) {
    int seg = kk >> 8, kin = kk & 255;
    float v = cb[(size_t)row * D_DIM + kin];
    float h = tf32_rna(v);
    return (seg == 1) ? tf32_rna(__fsub_rn(v, h)) : h;
}

// one block per 16-row tile; 3072 float4 per tile
__global__ void split_x_kernel(const float* __restrict__ x) {
    int rt = blockIdx.x;
    int tid = threadIdx.x;
#pragma unroll
    for (int j = 0; j < 12; j++) {
        int i = tid + j * 256;            // 0..3071
        int chunk = i >> 7;
        int r = i & 127;
        int lane = r & 31;
        int g = lane >> 2, t = lane & 3;
        int kb = chunk * 32 + (r >> 5) * 8 + t;
        float4 o;
        o.x = xa_val(x, rt * 16 + g,     kb);
        o.y = xa_val(x, rt * 16 + g + 8, kb);
        o.z = xa_val(x, rt * 16 + g,     kb + 4);
        o.w = xa_val(x, rt * 16 + g + 8, kb + 4);
        ((float4*)XA)[(size_t)rt * 3072 + i] = o;
    }
}

__global__ void split_c_kernel(const float* __restrict__ cb) {
    int ct = blockIdx.x;
    int tid = threadIdx.x;
#pragma unroll
    for (int j = 0; j < 12; j++) {
        int i = tid + j * 256;
        int chunk = i >> 7;
        int r = i & 127;
        int lane = r & 31;
        int g = lane >> 2, t = lane & 3;
        int kb = chunk * 32 + (r >> 5) * 8 + t;
        float4 o;
        o.x = cb_val(cb, ct * 16 + g,     kb);
        o.y = cb_val(cb, ct * 16 + g,     kb + 4);
        o.z = cb_val(cb, ct * 16 + g + 8, kb);
        o.w = cb_val(cb, ct * 16 + g + 8, kb + 4);
        ((float4*)CB)[(size_t)ct * 3072 + i] = o;
    }
}

// ---------------------------------------------------------------------------
// Main: mma.sync tf32 GEMM with packed-fragment smem (LDS.128 only).
// 512 threads, 16 warps (8m x 2n); per pass 256x128, K=768.
// ---------------------------------------------------------------------------
#define SM_A    0                              // 2 x 32768 B
#define SM_B    65536                          // 2 x 16384 B
#define SM_CN   98304                          // float[128]
#define SM_BS   98816                          // float[2][256]
#define SM_BI   100864                         // int[2][256]
#define SM_SS   102912                         // float[2][256]
#define SMEM_TOTAL 104960

__device__ __forceinline__ void load_chunk(u32 sbase, int buf, int chunk,
                                           int pass, int rowTileBase, int tid) {
#pragma unroll
    for (int j = 0; j < 4; j++) {              // A: 16 mt x 512 floats
        int i = tid + j * 512;                 // 0..2047 (16B units)
        int mt = i >> 7, rem = i & 127;
        const float* src = XA + (((size_t)(rowTileBase + mt) * NCHUNK + chunk) * 128 + rem) * 4;
        cp_async16(sbase + SM_A + buf * 32768 + i * 16, src);
    }
#pragma unroll
    for (int j = 0; j < 2; j++) {              // B: 8 nb x 512 floats
        int i = tid + j * 512;                 // 0..1023
        int nb = i >> 7, rem = i & 127;
        const float* src = CB + (((size_t)(pass * 8 + nb) * NCHUNK + chunk) * 128 + rem) * 4;
        cp_async16(sbase + SM_B + buf * 16384 + i * 16, src);
    }
    CP_COMMIT();
}

__global__ __launch_bounds__(512, 1)
void vq_mma_kernel(void) {
    extern __shared__ char smem[];
    const u32 sbase = smem_u32(smem);
    const int tid  = threadIdx.x;
    const int lane = tid & 31;
    const int g    = lane >> 2;
    const int t    = lane & 3;
    const int wid  = tid >> 5;        // 0..15
    const int wm   = wid >> 1;        // 0..7  -> rows wm*32
    const int wn   = wid & 1;         // 0..1  -> cols wn*64
    const int rowBase = blockIdx.x * BM;
    const int rowTileBase = blockIdx.x * (BM / 16);

    float* sCN = (float*)(smem + SM_CN);
    float* sBS = (float*)(smem + SM_BS);
    int*   sBI = (int*)(smem + SM_BI);
    float* sSS = (float*)(smem + SM_SS);

    float ax[4];
#pragma unroll
    for (int r = 0; r < 4; r++)
        ax[r] = g_xnorm[rowBase + wm * 32 + (r >> 1) * 16 + (r & 1) * 8 + g];

    float bs[4], ss[4];
    int   bi[4];
#pragma unroll
    for (int r = 0; r < 4; r++) { bs[r] = 3.4e38f; ss[r] = 3.4e38f; bi[r] = 0; }

    for (int pass = 0; pass < PASSES; pass++) {
        if (tid < BN) sCN[tid] = g_cnorm[pass * BN + tid];

        float acc[2][8][4];
#pragma unroll
        for (int m = 0; m < 2; m++)
#pragma unroll
            for (int nt = 0; nt < 8; nt++)
#pragma unroll
                for (int e = 0; e < 4; e++) acc[m][nt][e] = 0.f;

        load_chunk(sbase, 0, 0, pass, rowTileBase, tid);

        for (int c = 0; c < NCHUNK; c++) {
            if (c + 1 < NCHUNK) {
                load_chunk(sbase, (c + 1) & 1, c + 1, pass, rowTileBase, tid);
                CP_WAIT(1);
            } else {
                CP_WAIT(0);
            }
            __syncthreads();

            const float* Ab = (const float*)(smem + SM_A + (c & 1) * 32768);
            const float* Bb = (const float*)(smem + SM_B + (c & 1) * 16384);
#pragma unroll
            for (int s = 0; s < 4; s++) {
                float4 a0 = *(const float4*)(Ab + (wm * 2 + 0) * 512 + s * 128 + lane * 4);
                float4 a1 = *(const float4*)(Ab + (wm * 2 + 1) * 512 + s * 128 + lane * 4);
                u32 A0[4] = {__float_as_uint(a0.x), __float_as_uint(a0.y),
                             __float_as_uint(a0.z), __float_as_uint(a0.w)};
                u32 A1[4] = {__float_as_uint(a1.x), __float_as_uint(a1.y),
                             __float_as_uint(a1.z), __float_as_uint(a1.w)};
#pragma unroll
                for (int nb2 = 0; nb2 < 4; nb2++) {
                    float4 b = *(const float4*)(Bb + (wn * 4 + nb2) * 512 + s * 128 + lane * 4);
                    u32 b0 = __float_as_uint(b.x), b1 = __float_as_uint(b.y);
                    u32 b2 = __float_as_uint(b.z), b3 = __float_as_uint(b.w);
                    mma_tf32(acc[0][2 * nb2],     A0[0], A0[1], A0[2], A0[3], b0, b1);
                    mma_tf32(acc[1][2 * nb2],     A1[0], A1[1], A1[2], A1[3], b0, b1);
                    mma_tf32(acc[0][2 * nb2 + 1], A0[0], A0[1], A0[2], A0[3], b2, b3);
                    mma_tf32(acc[1][2 * nb2 + 1], A1[0], A1[1], A1[2], A1[3], b2, b3);
                }
            }
            __syncthreads();
        }

        // ---- FROZEN quantized score chain + top-2 running argmin
#pragma unroll
        for (int m = 0; m < 2; m++)
#pragma unroll
            for (int h = 0; h < 2; h++) {
                int r = m * 2 + h;
#pragma unroll
                for (int nt = 0; nt < 8; nt++)
#pragma unroll
                    for (int e = 0; e < 2; e++) {
                        float dot = acc[m][nt][h * 2 + e];
                        int cl = wn * 64 + nt * 8 + 2 * t + e;
                        float T  = __fadd_rn(ax[r], sCN[cl]);
                        float sc = __fsub_rn(T, __fmul_rn(2.0f, dot));
                        if (sc < bs[r]) {
                            ss[r] = bs[r]; bs[r] = sc; bi[r] = pass * BN + cl;
                        } else if (sc < ss[r]) {
                            ss[r] = sc;
                        }
                    }
            }
        __syncthreads();
    }

    // ---- cross-lane top-2 merge within 4-lane group
#pragma unroll
    for (int q = 1; q <= 2; q <<= 1) {
#pragma unroll
        for (int r = 0; r < 4; r++) {
            float ob = __shfl_xor_sync(0xffffffffu, bs[r], q);
            int   oi = __shfl_xor_sync(0xffffffffu, bi[r], q);
            float os = __shfl_xor_sync(0xffffffffu, ss[r], q);
            if (ob < bs[r] || (ob == bs[r] && oi < bi[r])) {
                ss[r] = fminf(os, bs[r]); bs[r] = ob; bi[r] = oi;
            } else {
                ss[r] = fminf(ss[r], ob);
            }
        }
    }
    if (t == 0) {
#pragma unroll
        for (int r = 0; r < 4; r++) {
            int row = wm * 32 + (r >> 1) * 16 + (r & 1) * 8 + g;
            sBS[wn * 256 + row] = bs[r];
            sBI[wn * 256 + row] = bi[r];
            sSS[wn * 256 + row] = ss[r];
        }
    }
    __syncthreads();
    if (tid < BM) {
        float b0 = sBS[tid], b1 = sBS[256 + tid];
        int   i0 = sBI[tid], i1 = sBI[256 + tid];
        float s0 = sSS[tid], s1 = sSS[256 + tid];
        float nb, ns; int ni;
        if (b1 < b0 || (b1 == b0 && i1 < i0)) { nb = b1; ni = i1; ns = fminf(s1, b0); }
        else                                  { nb = b0; ni = i0; ns = fminf(s0, b1); }
        g_widx[rowBase + tid] = ni;
        if (__fsub_rn(ns, nb) <= EPS_FLAG) {
            int slot = atomicAdd(&g_flagcnt, 1);
            g_flaglist[slot] = rowBase + tid;
        }
    }
}

// ---------------------------------------------------------------------------
// Rescue: exact fp32 re-scan (R5 sequential-k fmaf chain + frozen quantized
// score) over ALL 2048 codes for each flagged row. 8 rows per block batch.
// ---------------------------------------------------------------------------
__global__ __launch_bounds__(256, 2)
void rescue_kernel(const float* __restrict__ x, const float* __restrict__ cb) {
    __shared__ int   srows[8];
    __shared__ float sx[8][256];
    __shared__ float rv[256];
    __shared__ int   ri[256];

    const int tid = threadIdx.x;
    const int cnt = g_flagcnt;

    for (int base = blockIdx.x * 8; base < cnt; base += gridDim.x * 8) {
        if (tid < 8)
            srows[tid] = (base + tid < cnt) ? g_flaglist[base + tid] : g_flaglist[base];
        __syncthreads();
#pragma unroll 1
        for (int i = tid; i < 8 * 256; i += 256) {
            int rr = i >> 8, k = i & 255;
            sx[rr][k] = x[(size_t)srows[rr] * D_DIM + k];
        }
        __syncthreads();

        float acc[8][8];
#pragma unroll
        for (int jc = 0; jc < 8; jc++)
#pragma unroll
            for (int rr = 0; rr < 8; rr++) acc[jc][rr] = 0.f;

#pragma unroll 1
        for (int k4 = 0; k4 < 64; k4++) {
            float4 cv[8];
#pragma unroll
            for (int jc = 0; jc < 8; jc++)
                cv[jc] = *(const float4*)(cb + (size_t)(jc * 256 + tid) * D_DIM + k4 * 4);
#pragma unroll
            for (int rr = 0; rr < 8; rr++) {
                float x0 = sx[rr][k4 * 4 + 0];
                float x1 = sx[rr][k4 * 4 + 1];
                float x2 = sx[rr][k4 * 4 + 2];
                float x3 = sx[rr][k4 * 4 + 3];
#pragma unroll
                for (int jc = 0; jc < 8; jc++) {
                    float a = acc[jc][rr];
                    a = fmaf(x0, cv[jc].x, a);
                    a = fmaf(x1, cv[jc].y, a);
                    a = fmaf(x2, cv[jc].z, a);
                    a = fmaf(x3, cv[jc].w, a);
                    acc[jc][rr] = a;
                }
            }
        }

#pragma unroll 1
        for (int rr = 0; rr < 8; rr++) {
            int   grow = srows[rr];
            float an   = g_xnorm[grow];
            float lb = 3.4e38f;
            int   li = 0;
#pragma unroll
            for (int jc = 0; jc < 8; jc++) {
                int code = jc * 256 + tid;
                float T  = __fadd_rn(an, g_cnorm[code]);
                float sc = __fsub_rn(T, __fmul_rn(2.0f, acc[jc][rr]));
                if (sc < lb) { lb = sc; li = code; }
            }
            rv[tid] = lb; ri[tid] = li;
            __syncthreads();
#pragma unroll
            for (int s = 128; s > 0; s >>= 1) {
                if (tid < s) {
                    float ov = rv[tid + s]; int oi = ri[tid + s];
                    if (ov < rv[tid] || (ov == rv[tid] && oi < ri[tid])) {
                        rv[tid] = ov; ri[tid] = oi;
                    }
                }
                __syncthreads();
            }
            if (tid == 0 && base + rr < cnt) g_widx[grow] = ri[0];
            __syncthreads();
        }
        __syncthreads();
    }
}

// ---------------------------------------------------------------------------
// Gather + output (frozen rounding) + loss partials. 256 blocks x 128 rows.
// ---------------------------------------------------------------------------
__global__ __launch_bounds__(256, 2)
void gather_kernel(const float* __restrict__ x, const float* __restrict__ cb,
                   float* __restrict__ out) {
    __shared__ int   sw[128];
    __shared__ float sred[256];
    const int tid = threadIdx.x;
    const int rowBase = blockIdx.x * 128;

    if (tid < 128) sw[tid] = g_widx[rowBase + tid];
    __syncthreads();

    float lsum = 0.f;
#pragma unroll 1
    for (int i = tid; i < 128 * (D_DIM / 4); i += 256) {
        int row = i >> 6;
        int c4  = (i & 63) << 2;
        size_t goff = (size_t)(rowBase + row) * D_DIM + c4;
        float4 xv = *(const float4*)(x + goff);
        float4 cv = *(const float4*)(cb + (size_t)sw[row] * D_DIM + c4);
        float4 o;
        o.x = __fadd_rn(xv.x, __fsub_rn(cv.x, xv.x));
        o.y = __fadd_rn(xv.y, __fsub_rn(cv.y, xv.y));
        o.z = __fadd_rn(xv.z, __fsub_rn(cv.z, xv.z));
        o.w = __fadd_rn(xv.w, __fsub_rn(cv.w, xv.w));
        *(float4*)(out + goff) = o;
        float dx = __fsub_rn(xv.x, cv.x); lsum = fmaf(dx, dx, lsum);
        float dy = __fsub_rn(xv.y, cv.y); lsum = fmaf(dy, dy, lsum);
        float dz = __fsub_rn(xv.z, cv.z); lsum = fmaf(dz, dz, lsum);
        float dw = __fsub_rn(xv.w, cv.w); lsum = fmaf(dw, dw, lsum);
    }
    __syncthreads();
    sred[tid] = lsum;
    __syncthreads();
#pragma unroll
    for (int s = 128; s > 0; s >>= 1) {
        if (tid < s) sred[tid] += sred[tid + s];
        __syncthreads();
    }
    if (tid == 0) g_partial[blockIdx.x] = sred[0];
}

// ---------------------------------------------------------------------------
// Deterministic loss finalize. loss = 1.25 * mean((x-c)^2).
// ---------------------------------------------------------------------------
__global__ void loss_kernel(float* __restrict__ out, int out_size) {
    __shared__ double sd[256];
    int tid = threadIdx.x;
    sd[tid] = (double)g_partial[tid];
    __syncthreads();
#pragma unroll
    for (int s = 128; s > 0; s >>= 1) {
        if (tid < s) sd[tid] += sd[tid + s];
        __syncthreads();
    }
    if (tid == 0) {
        double mean = sd[0] / (double)((size_t)N_ROWS * D_DIM);
        out[out_size - 1] = (float)(1.25 * mean);
    }
}

// ---------------------------------------------------------------------------
extern "C" void kernel_launch(void* const* d_in, const int* in_sizes, int n_in,
                              void* d_out, int out_size) {
    const float* x  = (const float*)d_in[0];   // [N, D]
    const float* cb = (const float*)d_in[1];   // [K, D]
    float* out = (float*)d_out;                // [N*D] quantized + [1] loss

    (void)in_sizes; (void)n_in;

    cudaFuncSetAttribute(vq_mma_kernel, cudaFuncAttributeMaxDynamicSharedMemorySize,
                         SMEM_TOTAL);

    zero_kernel<<<1, 1>>>();
    norms_kernel<<<(N_ROWS + K_CODES) / 8, 256>>>(x, cb);
    split_x_kernel<<<N_ROWS / 16, 256>>>(x);
    split_c_kernel<<<K_CODES / 16, 256>>>(cb);
    vq_mma_kernel<<<NBLK, 512, SMEM_TOTAL>>>();
    rescue_kernel<<<256, 256>>>(x, cb);
    gather_kernel<<<GBLK, 256>>>(x, cb, out);
    loss_kernel<<<1, 256>>>(out, out_size);
}

// round 16
// speedup vs baseline: 2.0964x; 2.0964x over previous
#include <cuda_runtime.h>
#include <cuda_bf16.h>
#include <cstdint>

#define N_ROWS  32768
#define D_DIM   256
#define K_CODES 2048
#define BM      256                 // rows per CTA
#define BN      128                 // codes per pass tile
#define NBLK    (N_ROWS / BM)       // 128
#define PASSES  (K_CODES / BN)      // 16
#define NCHUNK  12                  // 768 bf16 elems / 64 per chunk
#define AST     36                  // smem A row stride (u32), 16B-aligned, conflict-free
#define BST     36
#define EPS_FLAG 1.2e-4f            // > 2 score-grid steps + margin (R14-proven)
#define GBLK    256

typedef unsigned int u32;

// static device scratch — bf16 pairs, k-major: 768 bf16 = 384 u32 per row.
// XA k-order: [xhi | xhi | xlo]   (seg = k/256)
// CB k-order: [chi | clo | chi]
__device__ u32 XAu[(size_t)N_ROWS * 384];
__device__ u32 CBu[(size_t)K_CODES * 384];
__device__ float g_xnorm[N_ROWS];
__device__ float g_cnorm[K_CODES];
__device__ float g_partial[GBLK];
__device__ int   g_widx[N_ROWS];
__device__ int   g_flaglist[N_ROWS];
__device__ int   g_flagcnt;

// ---------------- helpers (baseline PTX only) ------------------------------
__device__ __forceinline__ u32 smem_u32(const void* p) {
    u32 a;
    asm("{ .reg .u64 t; cvta.to.shared.u64 t, %1; cvt.u32.u64 %0, t; }" : "=r"(a) : "l"(p));
    return a;
}
__device__ __forceinline__ void cp_async16(u32 dst, const void* src) {
    asm volatile("cp.async.cg.shared.global [%0], [%1], 16;" :: "r"(dst), "l"(src));
}
#define CP_COMMIT()  asm volatile("cp.async.commit_group;")
#define CP_WAIT(n)   asm volatile("cp.async.wait_group %0;" :: "n"(n))

// m16n8k16 bf16 MMA (sm_80 baseline feature)
__device__ __forceinline__ void mma_bf16(float* c, const u32* a, u32 b0, u32 b1) {
    asm volatile(
        "mma.sync.aligned.m16n8k16.row.col.f32.bf16.bf16.f32 "
        "{%0,%1,%2,%3}, {%4,%5,%6,%7}, {%8,%9}, {%0,%1,%2,%3};"
        : "+f"(c[0]), "+f"(c[1]), "+f"(c[2]), "+f"(c[3])
        : "r"(a[0]), "r"(a[1]), "r"(a[2]), "r"(a[3]), "r"(b0), "r"(b1));
}

__global__ void zero_kernel() { g_flagcnt = 0; }

// ---------------------------------------------------------------------------
// FROZEN: bit-exact XLA row-sumsq (256-wide f32).
// ---------------------------------------------------------------------------
__device__ __forceinline__ float xla_row_sumsq(const float* __restrict__ row, int lane) {
    float s[4];
#pragma unroll
    for (int g = 0; g < 4; g++) {
        float x0 = row[64 * g + 2 * lane];
        float x1 = row[64 * g + 2 * lane + 1];
        s[g] = __fadd_rn(__fmul_rn(x0, x0), __fmul_rn(x1, x1));
    }
#pragma unroll
    for (int off = 16; off > 0; off >>= 1) {
#pragma unroll
        for (int g = 0; g < 4; g++)
            s[g] = __fadd_rn(s[g], __shfl_down_sync(0xffffffffu, s[g], off));
    }
    return __fadd_rn(__fadd_rn(s[0], s[2]), __fadd_rn(s[1], s[3]));
}

__global__ void norms_kernel(const float* __restrict__ x, const float* __restrict__ cb) {
    int warp = (blockIdx.x * blockDim.x + threadIdx.x) >> 5;
    int lane = threadIdx.x & 31;
    if (warp < N_ROWS) {
        float a = xla_row_sumsq(x + (size_t)warp * D_DIM, lane);
        if (lane == 0) g_xnorm[warp] = a;
    } else if (warp < N_ROWS + K_CODES) {
        int j = warp - N_ROWS;
        float b = xla_row_sumsq(cb + (size_t)j * D_DIM, lane);
        if (lane == 0) g_cnorm[j] = b;
    }
}

// ---------------------------------------------------------------------------
// bf16x3 split builders. One block per source row; 384 packed u32 per row.
// ---------------------------------------------------------------------------
__device__ __forceinline__ u32 pack_bf16(float v0, float v1, bool lo) {
    __nv_bfloat16 h0 = __float2bfloat16_rn(v0);
    __nv_bfloat16 h1 = __float2bfloat16_rn(v1);
    if (lo) {
        h0 = __float2bfloat16_rn(__fsub_rn(v0, __bfloat162float(h0)));
        h1 = __float2bfloat16_rn(__fsub_rn(v1, __bfloat162float(h1)));
    }
    return (u32)__bfloat16_as_ushort(h0) | ((u32)__bfloat16_as_ushort(h1) << 16);
}

__global__ void split_x_kernel(const float* __restrict__ x) {
    int row = blockIdx.x;
    const float* xr = x + (size_t)row * D_DIM;
    u32* dst = XAu + (size_t)row * 384;
    for (int j = threadIdx.x; j < 384; j += blockDim.x) {
        int seg = j >> 7;                  // 0,1 = hi ; 2 = lo
        int k2  = (j & 127) * 2;
        dst[j] = pack_bf16(xr[k2], xr[k2 + 1], seg == 2);
    }
}

__global__ void split_c_kernel(const float* __restrict__ cb) {
    int row = blockIdx.x;
    const float* cr = cb + (size_t)row * D_DIM;
    u32* dst = CBu + (size_t)row * 384;
    for (int j = threadIdx.x; j < 384; j += blockDim.x) {
        int seg = j >> 7;                  // 0,2 = hi ; 1 = lo
        int k2  = (j & 127) * 2;
        dst[j] = pack_bf16(cr[k2], cr[k2 + 1], seg == 1);
    }
}

// ---------------------------------------------------------------------------
// Main: mma.sync bf16 GEMM (256x128 per pass, K=768 bf16 in 12 chunks of 64)
// + frozen quantized argmin with top-2 tracking + flagging.
// 512 threads, 16 warps (8m x 2n).
// ---------------------------------------------------------------------------
#define SM_A    0                              // 2 x 36864 B
#define SM_B    73728                          // 2 x 18432 B
#define SM_CN   110592                         // float[128]
#define SM_BS   111104                         // float[2][256]
#define SM_BI   113152                         // int[2][256]
#define SM_SS   115200                         // float[2][256]
#define SMEM_TOTAL 117248

__device__ __forceinline__ void load_chunk(u32 sbase, int buf, int chunk,
                                           int pass, int rowBase, int tid) {
#pragma unroll
    for (int j = 0; j < 4; j++) {              // A: 256 rows x 8 x 16B
        int i = tid + j * 512;                 // 0..2047
        int row = i >> 3, u = i & 7;
        const u32* src = XAu + ((size_t)(rowBase + row) * 384 + chunk * 32 + u * 4);
        cp_async16(sbase + SM_A + buf * 36864 + (u32)(row * AST + u * 4) * 4, src);
    }
#pragma unroll
    for (int j = 0; j < 2; j++) {              // B: 128 rows x 8 x 16B
        int i = tid + j * 512;                 // 0..1023
        int row = i >> 3, u = i & 7;
        const u32* src = CBu + ((size_t)(pass * BN + row) * 384 + chunk * 32 + u * 4);
        cp_async16(sbase + SM_B + buf * 18432 + (u32)(row * BST + u * 4) * 4, src);
    }
    CP_COMMIT();
}

__global__ __launch_bounds__(512, 1)
void vq_mma_kernel(void) {
    extern __shared__ char smem[];
    const u32 sbase = smem_u32(smem);
    const int tid  = threadIdx.x;
    const int lane = tid & 31;
    const int g    = lane >> 2;
    const int t    = lane & 3;
    const int wid  = tid >> 5;        // 0..15
    const int wm   = wid >> 1;        // 0..7  -> rows wm*32
    const int wn   = wid & 1;         // 0..1  -> cols wn*64
    const int rowBase = blockIdx.x * BM;

    float* sCN = (float*)(smem + SM_CN);
    float* sBS = (float*)(smem + SM_BS);
    int*   sBI = (int*)(smem + SM_BI);
    float* sSS = (float*)(smem + SM_SS);

    float ax[4];
#pragma unroll
    for (int r = 0; r < 4; r++)
        ax[r] = g_xnorm[rowBase + wm * 32 + (r >> 1) * 16 + (r & 1) * 8 + g];

    float bs[4], ss[4];
    int   bi[4];
#pragma unroll
    for (int r = 0; r < 4; r++) { bs[r] = 3.4e38f; ss[r] = 3.4e38f; bi[r] = 0; }

    for (int pass = 0; pass < PASSES; pass++) {
        if (tid < BN) sCN[tid] = g_cnorm[pass * BN + tid];

        float acc[2][8][4];
#pragma unroll
        for (int m = 0; m < 2; m++)
#pragma unroll
            for (int nt = 0; nt < 8; nt++)
#pragma unroll
                for (int e = 0; e < 4; e++) acc[m][nt][e] = 0.f;

        load_chunk(sbase, 0, 0, pass, rowBase, tid);

        for (int c = 0; c < NCHUNK; c++) {
            if (c + 1 < NCHUNK) {
                load_chunk(sbase, (c + 1) & 1, c + 1, pass, rowBase, tid);
                CP_WAIT(1);
            } else {
                CP_WAIT(0);
            }
            __syncthreads();

            const u32* Ab = (const u32*)(smem + SM_A + (c & 1) * 36864);
            const u32* Bb = (const u32*)(smem + SM_B + (c & 1) * 18432);
#pragma unroll
            for (int s = 0; s < 4; s++) {          // 4 x k16 per chunk
                u32 a[2][4];
#pragma unroll
                for (int m = 0; m < 2; m++) {
                    const u32* pa = Ab + (wm * 32 + m * 16 + g) * AST + s * 8;
                    a[m][0] = pa[t];
                    a[m][1] = pa[8 * AST + t];
                    a[m][2] = pa[t + 4];
                    a[m][3] = pa[8 * AST + t + 4];
                }
#pragma unroll
                for (int nt = 0; nt < 8; nt++) {
                    const u32* pb = Bb + (wn * 64 + nt * 8 + g) * BST + s * 8 + t;
                    u32 b0 = pb[0];
                    u32 b1 = pb[4];
                    mma_bf16(acc[0][nt], a[0], b0, b1);
                    mma_bf16(acc[1][nt], a[1], b0, b1);
                }
            }
            __syncthreads();
        }

        // ---- FROZEN quantized score chain + top-2 running argmin
#pragma unroll
        for (int m = 0; m < 2; m++)
#pragma unroll
            for (int h = 0; h < 2; h++) {
                int r = m * 2 + h;
#pragma unroll
                for (int nt = 0; nt < 8; nt++)
#pragma unroll
                    for (int e = 0; e < 2; e++) {
                        float dot = acc[m][nt][h * 2 + e];
                        int cl = wn * 64 + nt * 8 + 2 * t + e;
                        float T  = __fadd_rn(ax[r], sCN[cl]);
                        float sc = __fsub_rn(T, __fmul_rn(2.0f, dot));
                        if (sc < bs[r]) {
                            ss[r] = bs[r]; bs[r] = sc; bi[r] = pass * BN + cl;
                        } else if (sc < ss[r]) {
                            ss[r] = sc;
                        }
                    }
            }
        __syncthreads();
    }

    // ---- cross-lane top-2 merge within 4-lane group
#pragma unroll
    for (int q = 1; q <= 2; q <<= 1) {
#pragma unroll
        for (int r = 0; r < 4; r++) {
            float ob = __shfl_xor_sync(0xffffffffu, bs[r], q);
            int   oi = __shfl_xor_sync(0xffffffffu, bi[r], q);
            float os = __shfl_xor_sync(0xffffffffu, ss[r], q);
            if (ob < bs[r] || (ob == bs[r] && oi < bi[r])) {
                ss[r] = fminf(os, bs[r]); bs[r] = ob; bi[r] = oi;
            } else {
                ss[r] = fminf(ss[r], ob);
            }
        }
    }
    if (t == 0) {
#pragma unroll
        for (int r = 0; r < 4; r++) {
            int row = wm * 32 + (r >> 1) * 16 + (r & 1) * 8 + g;
            sBS[wn * 256 + row] = bs[r];
            sBI[wn * 256 + row] = bi[r];
            sSS[wn * 256 + row] = ss[r];
        }
    }
    __syncthreads();
    if (tid < BM) {
        float b0 = sBS[tid], b1 = sBS[256 + tid];
        int   i0 = sBI[tid], i1 = sBI[256 + tid];
        float s0 = sSS[tid], s1 = sSS[256 + tid];
        float nb, ns; int ni;
        if (b1 < b0 || (b1 == b0 && i1 < i0)) { nb = b1; ni = i1; ns = fminf(s1, b0); }
        else                                  { nb = b0; ni = i0; ns = fminf(s0, b1); }
        g_widx[rowBase + tid] = ni;
        if (__fsub_rn(ns, nb) <= EPS_FLAG) {
            int slot = atomicAdd(&g_flagcnt, 1);
            g_flaglist[slot] = rowBase + tid;
        }
    }
}

// ---------------------------------------------------------------------------
// Rescue: exact fp32 re-scan (R5 sequential-k fmaf chain + frozen quantized
// score) over ALL 2048 codes for each flagged row. 8 rows per block batch.
// ---------------------------------------------------------------------------
__global__ __launch_bounds__(256, 2)
void rescue_kernel(const float* __restrict__ x, const float* __restrict__ cb) {
    __shared__ int   srows[8];
    __shared__ float sx[8][256];
    __shared__ float rv[256];
    __shared__ int   ri[256];

    const int tid = threadIdx.x;
    const int cnt = g_flagcnt;

    for (int base = blockIdx.x * 8; base < cnt; base += gridDim.x * 8) {
        if (tid < 8)
            srows[tid] = (base + tid < cnt) ? g_flaglist[base + tid] : g_flaglist[base];
        __syncthreads();
#pragma unroll 1
        for (int i = tid; i < 8 * 256; i += 256) {
            int rr = i >> 8, k = i & 255;
            sx[rr][k] = x[(size_t)srows[rr] * D_DIM + k];
        }
        __syncthreads();

        float acc[8][8];
#pragma unroll
        for (int jc = 0; jc < 8; jc++)
#pragma unroll
            for (int rr = 0; rr < 8; rr++) acc[jc][rr] = 0.f;

#pragma unroll 1
        for (int k4 = 0; k4 < 64; k4++) {
            float4 cv[8];
#pragma unroll
            for (int jc = 0; jc < 8; jc++)
                cv[jc] = *(const float4*)(cb + (size_t)(jc * 256 + tid) * D_DIM + k4 * 4);
#pragma unroll
            for (int rr = 0; rr < 8; rr++) {
                float x0 = sx[rr][k4 * 4 + 0];
                float x1 = sx[rr][k4 * 4 + 1];
                float x2 = sx[rr][k4 * 4 + 2];
                float x3 = sx[rr][k4 * 4 + 3];
#pragma unroll
                for (int jc = 0; jc < 8; jc++) {
                    float a = acc[jc][rr];
                    a = fmaf(x0, cv[jc].x, a);
                    a = fmaf(x1, cv[jc].y, a);
                    a = fmaf(x2, cv[jc].z, a);
                    a = fmaf(x3, cv[jc].w, a);
                    acc[jc][rr] = a;
                }
            }
        }

#pragma unroll 1
        for (int rr = 0; rr < 8; rr++) {
            int   grow = srows[rr];
            float an   = g_xnorm[grow];
            float lb = 3.4e38f;
            int   li = 0;
#pragma unroll
            for (int jc = 0; jc < 8; jc++) {
                int code = jc * 256 + tid;
                float T  = __fadd_rn(an, g_cnorm[code]);
                float sc = __fsub_rn(T, __fmul_rn(2.0f, acc[jc][rr]));
                if (sc < lb) { lb = sc; li = code; }
            }
            rv[tid] = lb; ri[tid] = li;
            __syncthreads();
#pragma unroll
            for (int s = 128; s > 0; s >>= 1) {
                if (tid < s) {
                    float ov = rv[tid + s]; int oi = ri[tid + s];
                    if (ov < rv[tid] || (ov == rv[tid] && oi < ri[tid])) {
                        rv[tid] = ov; ri[tid] = oi;
                    }
                }
                __syncthreads();
            }
            if (tid == 0 && base + rr < cnt) g_widx[grow] = ri[0];
            __syncthreads();
        }
        __syncthreads();
    }
}

// ---------------------------------------------------------------------------
// Gather + output (frozen rounding) + loss partials. 256 blocks x 128 rows.
// ---------------------------------------------------------------------------
__global__ __launch_bounds__(256, 2)
void gather_kernel(const float* __restrict__ x, const float* __restrict__ cb,
                   float* __restrict__ out) {
    __shared__ int   sw[128];
    __shared__ float sred[256];
    const int tid = threadIdx.x;
    const int rowBase = blockIdx.x * 128;

    if (tid < 128) sw[tid] = g_widx[rowBase + tid];
    __syncthreads();

    float lsum = 0.f;
#pragma unroll 1
    for (int i = tid; i < 128 * (D_DIM / 4); i += 256) {
        int row = i >> 6;
        int c4  = (i & 63) << 2;
        size_t goff = (size_t)(rowBase + row) * D_DIM + c4;
        float4 xv = *(const float4*)(x + goff);
        float4 cv = *(const float4*)(cb + (size_t)sw[row] * D_DIM + c4);
        float4 o;
        o.x = __fadd_rn(xv.x, __fsub_rn(cv.x, xv.x));
        o.y = __fadd_rn(xv.y, __fsub_rn(cv.y, xv.y));
        o.z = __fadd_rn(xv.z, __fsub_rn(cv.z, xv.z));
        o.w = __fadd_rn(xv.w, __fsub_rn(cv.w, xv.w));
        *(float4*)(out + goff) = o;
        float dx = __fsub_rn(xv.x, cv.x); lsum = fmaf(dx, dx, lsum);
        float dy = __fsub_rn(xv.y, cv.y); lsum = fmaf(dy, dy, lsum);
        float dz = __fsub_rn(xv.z, cv.z); lsum = fmaf(dz, dz, lsum);
        float dw = __fsub_rn(xv.w, cv.w); lsum = fmaf(dw, dw, lsum);
    }
    __syncthreads();
    sred[tid] = lsum;
    __syncthreads();
#pragma unroll
    for (int s = 128; s > 0; s >>= 1) {
        if (tid < s) sred[tid] += sred[tid + s];
        __syncthreads();
    }
    if (tid == 0) g_partial[blockIdx.x] = sred[0];
}

// ---------------------------------------------------------------------------
// Deterministic loss finalize. loss = 1.25 * mean((x-c)^2).
// ---------------------------------------------------------------------------
__global__ void loss_kernel(float* __restrict__ out, int out_size) {
    __shared__ double sd[256];
    int tid = threadIdx.x;
    sd[tid] = (double)g_partial[tid];
    __syncthreads();
#pragma unroll
    for (int s = 128; s > 0; s >>= 1) {
        if (tid < s) sd[tid] += sd[tid + s];
        __syncthreads();
    }
    if (tid == 0) {
        double mean = sd[0] / (double)((size_t)N_ROWS * D_DIM);
        out[out_size - 1] = (float)(1.25 * mean);
    }
}

// ---------------------------------------------------------------------------
extern "C" void kernel_launch(void* const* d_in, const int* in_sizes, int n_in,
                              void* d_out, int out_size) {
    const float* x  = (const float*)d_in[0];   // [N, D]
    const float* cb = (const float*)d_in[1];   // [K, D]
    float* out = (float*)d_out;                // [N*D] quantized + [1] loss

    (void)in_sizes; (void)n_in;

    cudaFuncSetAttribute(vq_mma_kernel, cudaFuncAttributeMaxDynamicSharedMemorySize,
                         SMEM_TOTAL);

    zero_kernel<<<1, 1>>>();
    norms_kernel<<<(N_ROWS + K_CODES) / 8, 256>>>(x, cb);
    split_x_kernel<<<N_ROWS, 256>>>(x);
    split_c_kernel<<<K_CODES, 256>>>(cb);
    vq_mma_kernel<<<NBLK, 512, SMEM_TOTAL>>>();
    rescue_kernel<<<256, 256>>>(x, cb);
    gather_kernel<<<GBLK, 256>>>(x, cb, out);
    loss_kernel<<<1, 256>>>(out, out_size);
}